// round 13
// baseline (speedup 1.0000x reference)
#include <cuda_runtime.h>
#include <math.h>

// Problem constants
#define N_POINTS 4096
#define N_VIEWS  4
#define IMG_H    128
#define IMG_W    128
#define N_PIX    (N_VIEWS * IMG_H * IMG_W)   // 65536
#define TOPK     5
#define R2F      0.0004f     // 0.02^2

#define NTHREADS 512
#define ROWS_PER_BLOCK 4                      // strip height
#define BLOCKS_PER_VIEW (IMG_H / ROWS_PER_BLOCK)   // 32
#define NBLOCKS (N_VIEWS * BLOCKS_PER_VIEW)        // 128
#define PTS_PER_THREAD (N_POINTS / NTHREADS)       // 8

// SMEM hit lists: 64 groups of 8 pixels, CAP entries each
#define NGROUPS 64
#define GCAP    96
#define SMEM_BYTES (NGROUPS * GCAP * 16)

// cos(15deg), sin(15deg)
#define CE 0.96592582628906831f
#define SE 0.25881904510252074f

// Camera axes per view (columns of R): X_view = pcd . axis + T, T = (0,0,1.5)
__constant__ float c_ax[N_VIEWS][3] = {
    {-1.f, 0.f, 0.f}, {0.f, 0.f, 1.f}, {1.f, 0.f, 0.f}, {0.f, 0.f, -1.f}};
__constant__ float c_ay[N_VIEWS][3] = {
    {0.f, CE, -SE}, {-SE, CE, 0.f}, {0.f, CE, SE}, {SE, CE, 0.f}};
__constant__ float c_az[N_VIEWS][3] = {
    {0.f, -SE, -CE}, {-CE, -SE, 0.f}, {0.f, -SE, CE}, {CE, -SE, 0.f}};

__global__ void __launch_bounds__(NTHREADS)
fused_kernel(const float* __restrict__ pcd,
             const float* __restrict__ displace,
             const float* __restrict__ init_colors,
             float* __restrict__ out) {
    extern __shared__ float4 s_list[];            // [NGROUPS][GCAP]
    __shared__ int s_gcnt[NGROUPS];

    const int tid = threadIdx.x;
    const int v       = blockIdx.x >> 5;          // view
    const int rowbase = (blockIdx.x & 31) * ROWS_PER_BLOCK;

    if (tid < NGROUPS) s_gcnt[tid] = 0;
    __syncthreads();

    // colors_ output tail: 32 points per block
    if (tid < 32) {
        int n = blockIdx.x * 32 + tid;
        out[(size_t)N_PIX * 3 + n] =
            1.0f / (1.0f + expf(-(init_colors[n] + displace[n])));
    }

    const float ax0 = c_ax[v][0], ax1 = c_ax[v][1], ax2 = c_ax[v][2];
    const float ay0 = c_ay[v][0], ay1 = c_ay[v][1], ay2 = c_ay[v][2];
    const float az0 = c_az[v][0], az1 = c_az[v][1], az2 = c_az[v][2];

    const float inv128 = 0.0078125f;
    const float rexp = 0.0201f;
    // strip py window (yf decreasing in yi)
    const float strip_yhi = 1.0f - (float)(2 * rowbase + 1) * inv128 + rexp;
    const float strip_ylo = 1.0f - (float)(2 * (rowbase + 3) + 1) * inv128 - rexp;

    // ---------------- Phase 1: transform all points, scatter strip hits -------
#pragma unroll
    for (int k = 0; k < PTS_PER_THREAD; k++) {
        int n = tid + k * NTHREADS;
        float x = pcd[3 * n + 0];
        float y = pcd[3 * n + 1];
        float z = pcd[3 * n + 2];

        float px = x * ax0 + y * ax1 + z * ax2;
        float py = x * ay0 + y * ay1 + z * ay2;
        float zv = x * az0 + y * az1 + z * az2 + 1.5f;
        float pz = (zv - 0.01f) / 99.99f;

        if (pz <= 0.0f || py < strip_ylo || py > strip_yhi) continue;

        float col = 1.0f / (1.0f + expf(-(init_colors[n] + displace[n])));

        int ilo = max(0,   (int)ceilf ((1.0f - px - rexp) * 64.0f - 0.5f));
        int ihi = min(127, (int)floorf((1.0f - px + rexp) * 64.0f - 0.5f));
        int jlo = max(rowbase,     (int)ceilf ((1.0f - py - rexp) * 64.0f - 0.5f));
        int jhi = min(rowbase + 3, (int)floorf((1.0f - py + rexp) * 64.0f - 0.5f));
        if (ilo > ihi || jlo > jhi) continue;

#pragma unroll
        for (int dj = 0; dj < 3; dj++) {
            int yi = jlo + dj;
            if (yi > jhi) break;
            float yf = 1.0f - (float)(2 * yi + 1) * inv128;
            float dy = py - yf;
            float dy2 = dy * dy;
#pragma unroll
            for (int di = 0; di < 3; di++) {
                int xi = ilo + di;
                if (xi > ihi) break;
                float xf = 1.0f - (float)(2 * xi + 1) * inv128;
                float dx = px - xf;
                float d2 = fmaf(dx, dx, dy2);
                if (d2 < R2F) {
                    int pl = (yi - rowbase) * IMG_W + xi;    // local pixel 0..511
                    int g  = pl >> 3;                        // 8-px group
                    int s  = atomicAdd(&s_gcnt[g], 1);
                    if (s < GCAP)
                        s_list[g * GCAP + s] =
                            make_float4(pz, 1.0f - d2 / R2F, col,
                                        __int_as_float(pl));
                }
            }
        }
    }
    __syncthreads();

    // ---------------- Phase 2: per-pixel select top-5 + composite -------------
    const int pl  = tid;                 // local pixel
    const int g   = pl >> 3;
    int m = s_gcnt[g];
    if (m > GCAP) m = GCAP;

    const float INF = __int_as_float(0x7f800000);
    float zk[TOPK], ak[TOPK], ck[TOPK];
#pragma unroll
    for (int k = 0; k < TOPK; k++) { zk[k] = INF; ak[k] = 0.0f; ck[k] = 0.0f; }

    const float4* __restrict__ lst = &s_list[g * GCAP];
#pragma unroll 4
    for (int j = 0; j < m; j++) {
        float4 h = lst[j];
        if (__float_as_int(h.w) == pl) {
            float nz = h.x, na = h.y, nc = h.z;
#pragma unroll
            for (int k = 0; k < TOPK; k++) {
                if (nz < zk[k]) {
                    float t;
                    t = zk[k]; zk[k] = nz; nz = t;
                    t = ak[k]; ak[k] = na; na = t;
                    t = ck[k]; ck[k] = nc; nc = t;
                }
            }
        }
    }

    // front-to-back over-composite (empty slots contribute 0)
    float trans = 1.0f, pixv = 0.0f;
#pragma unroll
    for (int k = 0; k < TOPK; k++) {
        pixv += ak[k] * trans * ck[k];
        trans *= (1.0f - ak[k]);
    }

    int p = ((v * IMG_H) + rowbase + (pl >> 7)) * IMG_W + (pl & 127);
    int base = p * 3;
    out[base + 0] = pixv;
    out[base + 1] = pixv;
    out[base + 2] = pixv;
}

extern "C" void kernel_launch(void* const* d_in, const int* in_sizes, int n_in,
                              void* d_out, int out_size) {
    const float* pcd         = (const float*)d_in[0];
    const float* displace    = (const float*)d_in[1];
    const float* init_colors = (const float*)d_in[2];
    float* out = (float*)d_out;

    cudaFuncSetAttribute(fused_kernel,
                         cudaFuncAttributeMaxDynamicSharedMemorySize, SMEM_BYTES);
    fused_kernel<<<NBLOCKS, NTHREADS, SMEM_BYTES>>>(pcd, displace, init_colors, out);
}

// round 14
// speedup vs baseline: 2.1166x; 2.1166x over previous
#include <cuda_runtime.h>
#include <math.h>

// Problem constants
#define N_POINTS 4096
#define N_VIEWS  4
#define IMG_H    128
#define IMG_W    128
#define N_PIX    (N_VIEWS * IMG_H * IMG_W)   // 65536
#define TOPK     5
#define R2F      0.0004f     // 0.02^2
#define CAP      40          // per-pixel hit capacity (max observed ~20)

// cos(15deg), sin(15deg)
#define CE 0.96592582628906831f
#define SE 0.25881904510252074f

// Camera axes per view (columns of R): X_view = pcd . axis + T, T = (0,0,1.5)
__constant__ float c_ax[N_VIEWS][3] = {
    {-1.f, 0.f, 0.f}, {0.f, 0.f, 1.f}, {1.f, 0.f, 0.f}, {0.f, 0.f, -1.f}};
__constant__ float c_ay[N_VIEWS][3] = {
    {0.f, CE, -SE}, {-SE, CE, 0.f}, {0.f, CE, SE}, {SE, CE, 0.f}};
__constant__ float c_az[N_VIEWS][3] = {
    {0.f, -SE, -CE}, {-CE, -SE, 0.f}, {0.f, -SE, CE}, {CE, -SE, 0.f}};

// Plane-major per-pixel hit lists: hit j of pixel p at g_hits[j][p].
__device__ float4 g_hits[CAP][N_PIX];
__device__ int    g_hcnt[N_PIX];      // zero-init at load; raster resets after read

// One thread per (point, view). 4 consecutive threads share a point.
__global__ void __launch_bounds__(256)
prep_kernel(const float* __restrict__ pcd,
            const float* __restrict__ displace,
            const float* __restrict__ init_colors,
            float* __restrict__ out_colors) {
    // Release dependent (raster) launch immediately: its CTA dispatch + ramp
    // overlaps our execution; its griddepcontrol.wait still orders memory.
    asm volatile("griddepcontrol.launch_dependents;");

    int t = blockIdx.x * blockDim.x + threadIdx.x;
    if (t >= N_POINTS * N_VIEWS) return;
    int n = t >> 2;
    int v = t & 3;

    float x = pcd[3 * n + 0];
    float y = pcd[3 * n + 1];
    float z = pcd[3 * n + 2];
    float col = 1.0f / (1.0f + expf(-(init_colors[n] + displace[n])));
    if (v == 0) out_colors[n] = col;

    float px = x * c_ax[v][0] + y * c_ax[v][1] + z * c_ax[v][2];
    float py = x * c_ay[v][0] + y * c_ay[v][1] + z * c_ay[v][2];
    float zv = x * c_az[v][0] + y * c_az[v][1] + z * c_az[v][2] + 1.5f;
    float pz = (zv - 0.01f) / 99.99f;
    if (pz <= 0.0f) return;

    // pixel-center bbox: xf(xi) = 1 - (2xi+1)/128; disk spans <= 3 centers/axis
    const float rexp = 0.0201f;
    int ilo = max(0,   (int)ceilf ((1.0f - px - rexp) * 64.0f - 0.5f));
    int ihi = min(127, (int)floorf((1.0f - px + rexp) * 64.0f - 0.5f));
    int jlo = max(0,   (int)ceilf ((1.0f - py - rexp) * 64.0f - 0.5f));
    int jhi = min(127, (int)floorf((1.0f - py + rexp) * 64.0f - 0.5f));

    const float inv128 = 0.0078125f;

    // Fully unrolled 3x3 predicated scatter: 9 independent tests,
    // independent atomics issued back-to-back (latency overlapped).
    int   pp[9];
    float aa[9];
    bool  ok[9];
#pragma unroll
    for (int dj = 0; dj < 3; dj++) {
        int yi = jlo + dj;
        float yf = 1.0f - (float)(2 * yi + 1) * inv128;
        float dy = py - yf;
        float dy2 = dy * dy;
#pragma unroll
        for (int di = 0; di < 3; di++) {
            int e = dj * 3 + di;
            int xi = ilo + di;
            float xf = 1.0f - (float)(2 * xi + 1) * inv128;
            float dx = px - xf;
            float d2 = fmaf(dx, dx, dy2);
            ok[e] = (yi <= jhi) && (xi <= ihi) && (d2 < R2F);
            pp[e] = ((v * IMG_H) + yi) * IMG_W + xi;
            aa[e] = 1.0f - d2 / R2F;
        }
    }
    int ss[9];
#pragma unroll
    for (int e = 0; e < 9; e++)
        ss[e] = ok[e] ? atomicAdd(&g_hcnt[pp[e]], 1) : CAP;
#pragma unroll
    for (int e = 0; e < 9; e++)
        if (ss[e] < CAP)
            g_hits[ss[e]][pp[e]] = make_float4(pz, aa[e], col, 0.0f);
}

// One thread per pixel: gather own hits (plane-major, coalesced), top-5, composite.
// Launched with PDL: CTAs come up during prep; wait before touching prep data.
__global__ void __launch_bounds__(512) raster_kernel(float* __restrict__ out) {
    const int p = blockIdx.x * 512 + threadIdx.x;

    // Everything independent of prep output happens pre-wait (overlapped).
    const float INF = __int_as_float(0x7f800000);
    float zk[TOPK], ak[TOPK], ck[TOPK];
#pragma unroll
    for (int k = 0; k < TOPK; k++) { zk[k] = INF; ak[k] = 0.0f; ck[k] = 0.0f; }

    // Wait for prep's memory to be visible.
    asm volatile("griddepcontrol.wait;" ::: "memory");

    // count and plane-0 hit load concurrently (independent addresses)
    int n = g_hcnt[p];
    float4 h0 = g_hits[0][p];
    g_hcnt[p] = 0;                 // reset for next graph replay (same thread: ordered)
    if (n > CAP) n = CAP;

    if (n > 0) { zk[0] = h0.x; ak[0] = h0.y; ck[0] = h0.z; }

    // remaining hits (rare: ~30% of pixels have n>1)
#pragma unroll 2
    for (int j = 1; j < n; j++) {
        float4 h = g_hits[j][p];
        float nz = h.x, na = h.y, nc = h.z;
#pragma unroll
        for (int k = 0; k < TOPK; k++) {
            if (nz < zk[k]) {
                float t;
                t = zk[k]; zk[k] = nz; nz = t;
                t = ak[k]; ak[k] = na; na = t;
                t = ck[k]; ck[k] = nc; nc = t;
            }
        }
    }

    // front-to-back over-composite (empty slots contribute 0)
    float trans = 1.0f, pixv = 0.0f;
#pragma unroll
    for (int k = 0; k < TOPK; k++) {
        pixv += ak[k] * trans * ck[k];
        trans *= (1.0f - ak[k]);
    }

    int base = p * 3;
    out[base + 0] = pixv;
    out[base + 1] = pixv;
    out[base + 2] = pixv;
}

extern "C" void kernel_launch(void* const* d_in, const int* in_sizes, int n_in,
                              void* d_out, int out_size) {
    const float* pcd         = (const float*)d_in[0];
    const float* displace    = (const float*)d_in[1];
    const float* init_colors = (const float*)d_in[2];
    float* out = (float*)d_out;

    // colors_ tail lives after the 4*128*128*3 image block
    float* out_colors = out + (size_t)N_PIX * 3;

    prep_kernel<<<(N_POINTS * N_VIEWS + 255) / 256, 256>>>(pcd, displace, init_colors, out_colors);

    // Raster with Programmatic Dependent Launch: dispatch overlaps prep.
    cudaLaunchConfig_t cfg = {};
    cfg.gridDim  = dim3(N_PIX / 512, 1, 1);
    cfg.blockDim = dim3(512, 1, 1);
    cudaLaunchAttribute attr[1];
    attr[0].id = cudaLaunchAttributeProgrammaticStreamSerialization;
    attr[0].val.programmaticStreamSerializationAllowed = 1;
    cfg.attrs = attr;
    cfg.numAttrs = 1;
    cudaLaunchKernelEx(&cfg, raster_kernel, out);
}